// round 1
// baseline (speedup 1.0000x reference)
#include <cuda_runtime.h>
#include <math.h>
#include <float.h>

// Problem constants
#define BT   4096
#define KS   2048      // student hidden
#define KT   4096      // teacher hidden
#define VOC  32000
// Tiling
#define BM   128
#define BN   128
#define BKK  16
#define TM   8
#define TN   8
#define NTILES 250     // 32000 / 128
#define NPAD   256     // padded chunk stride for coalesced combine reads

// Scratch: per-(row, vtile) partials. 5 * 4096 * 256 * 4B = 21 MB (static, no alloc).
__device__ float g_m [BT * NPAD];
__device__ float g_z [BT * NPAD];
__device__ float g_d [BT * NPAD];
__device__ float g_ss[BT * NPAD];
__device__ float g_tt[BT * NPAD];
__device__ float g_row[BT * 2];   // per-row {ce, cos}

// ---------------------------------------------------------------------------
// Classic smem-tiled fp32 GEMM core: C[128][128] = A[row0..][K] * W[col0..][K]^T
// As stored [BM][BKK+1] (broadcast reads across tx), Bs stored [BKK][BN]
// (transposed, float4 inner-loop reads).
// ---------------------------------------------------------------------------
__device__ __forceinline__ void gemm_tile(
    const float* __restrict__ A, const float* __restrict__ W, int K,
    int row0, int col0, float (&acc)[TM][TN],
    float* As, float* Bs, int tid, int tx, int ty)
{
#pragma unroll
    for (int i = 0; i < TM; i++)
#pragma unroll
        for (int j = 0; j < TN; j++) acc[i][j] = 0.f;

    const int lr = tid >> 2;          // 0..63
    const int lc = (tid & 3) << 2;    // 0,4,8,12

    for (int kk = 0; kk < K; kk += BKK) {
        __syncthreads();   // previous compute phase done before overwrite
#pragma unroll
        for (int h = 0; h < 2; h++) {
            int r = lr + h * 64;
            float4 va = *reinterpret_cast<const float4*>(
                &A[(size_t)(row0 + r) * K + kk + lc]);
            As[r * (BKK + 1) + lc + 0] = va.x;
            As[r * (BKK + 1) + lc + 1] = va.y;
            As[r * (BKK + 1) + lc + 2] = va.z;
            As[r * (BKK + 1) + lc + 3] = va.w;
            float4 vb = *reinterpret_cast<const float4*>(
                &W[(size_t)(col0 + r) * K + kk + lc]);
            Bs[(lc + 0) * BN + r] = vb.x;
            Bs[(lc + 1) * BN + r] = vb.y;
            Bs[(lc + 2) * BN + r] = vb.z;
            Bs[(lc + 3) * BN + r] = vb.w;
        }
        __syncthreads();
#pragma unroll
        for (int k = 0; k < BKK; k++) {
            float a[TM];
#pragma unroll
            for (int i = 0; i < TM; i++)
                a[i] = As[(ty * TM + i) * (BKK + 1) + k];
            float4 b0 = *reinterpret_cast<const float4*>(&Bs[k * BN + tx * TN]);
            float4 b1 = *reinterpret_cast<const float4*>(&Bs[k * BN + tx * TN + 4]);
            float b[TN] = {b0.x, b0.y, b0.z, b0.w, b1.x, b1.y, b1.z, b1.w};
#pragma unroll
            for (int i = 0; i < TM; i++)
#pragma unroll
                for (int j = 0; j < TN; j++)
                    acc[i][j] = fmaf(a[i], b[j], acc[i][j]);
        }
    }
}

// ---------------------------------------------------------------------------
// K1: per (vtile, mtile): student GEMM -> stage S in smem -> teacher GEMM ->
// fused per-row partials -> shuffle-reduce across column threads -> scratch.
// ---------------------------------------------------------------------------
__global__ void __launch_bounds__(256, 2)
fused_logits_kernel(const float* __restrict__ s_in, const float* __restrict__ t_in,
                    const float* __restrict__ s_w,  const float* __restrict__ t_w)
{
    extern __shared__ float sm[];
    float* As  = sm;                       // BM*(BKK+1)
    float* Bs  = As + BM * (BKK + 1);      // BKK*BN
    float* Ssm = Bs + BKK * BN;            // BM*BN (staged student logits)

    const int nt = blockIdx.x;             // v-tile 0..249
    const int mt = blockIdx.y;             // m-tile 0..31
    const int row0 = mt * BM, col0 = nt * BN;
    const int tid = threadIdx.x;
    const int tx = tid & 15, ty = tid >> 4;

    float acc[TM][TN];

    // ---- student logits tile ----
    gemm_tile(s_in, s_w, KS, row0, col0, acc, As, Bs, tid, tx, ty);
#pragma unroll
    for (int i = 0; i < TM; i++) {
        *reinterpret_cast<float4*>(&Ssm[(ty * TM + i) * BN + tx * TN]) =
            make_float4(acc[i][0], acc[i][1], acc[i][2], acc[i][3]);
        *reinterpret_cast<float4*>(&Ssm[(ty * TM + i) * BN + tx * TN + 4]) =
            make_float4(acc[i][4], acc[i][5], acc[i][6], acc[i][7]);
    }
    // (no sync needed: each thread re-reads only its own staged values)

    // ---- teacher logits tile (reuses acc registers, As/Bs smem) ----
    gemm_tile(t_in, t_w, KT, row0, col0, acc, As, Bs, tid, tx, ty);

    // ---- fused partial reductions over this 128x128 tile ----
    float rm[TM], rz[TM], rd[TM], rs[TM], rt[TM];
#pragma unroll
    for (int i = 0; i < TM; i++) {
        float s[TN];
        float4 s0 = *reinterpret_cast<const float4*>(&Ssm[(ty * TM + i) * BN + tx * TN]);
        float4 s1 = *reinterpret_cast<const float4*>(&Ssm[(ty * TM + i) * BN + tx * TN + 4]);
        s[0]=s0.x; s[1]=s0.y; s[2]=s0.z; s[3]=s0.w;
        s[4]=s1.x; s[5]=s1.y; s[6]=s1.z; s[7]=s1.w;

        float mx = s[0];
#pragma unroll
        for (int j = 1; j < TN; j++) mx = fmaxf(mx, s[j]);
        float z = 0.f, d = 0.f, ssq = 0.f, tsq = 0.f;
#pragma unroll
        for (int j = 0; j < TN; j++) {
            float tv = acc[i][j];
            z   += __expf(s[j] - mx);
            d    = fmaf(s[j], tv, d);
            ssq  = fmaf(s[j], s[j], ssq);
            tsq  = fmaf(tv, tv, tsq);
        }
        rm[i]=mx; rz[i]=z; rd[i]=d; rs[i]=ssq; rt[i]=tsq;
    }
    // reduce across the 16 tx lanes (xor butterfly stays within half-warp)
#pragma unroll
    for (int off = 1; off < 16; off <<= 1) {
#pragma unroll
        for (int i = 0; i < TM; i++) {
            float om = __shfl_xor_sync(0xffffffffu, rm[i], off);
            float oz = __shfl_xor_sync(0xffffffffu, rz[i], off);
            float od = __shfl_xor_sync(0xffffffffu, rd[i], off);
            float os = __shfl_xor_sync(0xffffffffu, rs[i], off);
            float ot = __shfl_xor_sync(0xffffffffu, rt[i], off);
            float nm = fmaxf(rm[i], om);
            rz[i] = rz[i] * __expf(rm[i] - nm) + oz * __expf(om - nm);
            rm[i] = nm;
            rd[i] += od; rs[i] += os; rt[i] += ot;
        }
    }
    if (tx == 0) {
#pragma unroll
        for (int i = 0; i < TM; i++) {
            int row = row0 + ty * TM + i;
            size_t idx = (size_t)row * NPAD + nt;
            g_m[idx]  = rm[i];
            g_z[idx]  = rz[i];
            g_d[idx]  = rd[i];
            g_ss[idx] = rs[i];
            g_tt[idx] = rt[i];
        }
    }
}

// ---------------------------------------------------------------------------
// K2: one warp per row. Merge 250 v-tile partials (online logsumexp), compute
// target logit directly (2048-dot), emit per-row {ce, cos}.
// ---------------------------------------------------------------------------
__global__ void combine_kernel(const int* __restrict__ tgt,
                               const float* __restrict__ s_in,
                               const float* __restrict__ s_w)
{
    int gw   = (blockIdx.x * blockDim.x + threadIdx.x) >> 5;
    int lane = threadIdx.x & 31;
    if (gw >= BT) return;
    const int row = gw;

    float m = -FLT_MAX, z = 0.f, d = 0.f, ssq = 0.f, tsq = 0.f;
    for (int n = lane; n < NTILES; n += 32) {
        size_t idx = (size_t)row * NPAD + n;
        float om = g_m[idx], oz = g_z[idx];
        float nm = fmaxf(m, om);
        z = z * __expf(m - nm) + oz * __expf(om - nm);
        m = nm;
        d += g_d[idx]; ssq += g_ss[idx]; tsq += g_tt[idx];
    }
#pragma unroll
    for (int off = 16; off > 0; off >>= 1) {
        float om = __shfl_xor_sync(0xffffffffu, m, off);
        float oz = __shfl_xor_sync(0xffffffffu, z, off);
        float od = __shfl_xor_sync(0xffffffffu, d, off);
        float os = __shfl_xor_sync(0xffffffffu, ssq, off);
        float ot = __shfl_xor_sync(0xffffffffu, tsq, off);
        float nm = fmaxf(m, om);
        z = z * __expf(m - nm) + oz * __expf(om - nm);
        m = nm;
        d += od; ssq += os; tsq += ot;
    }

    // Target dtype detection: int64 layout => tgt[1] is high word of -100 => -1.
    bool is64 = (tgt[1] == -1);
    int t = is64 ? tgt[2 * row] : tgt[row];

    float ce = 0.f;
    if (t >= 0) {   // valid (ignore_index = -100)
        float p = 0.f;
        const float* a = s_in + (size_t)row * KS;
        const float* w = s_w  + (size_t)t   * KS;
        for (int k = lane * 4; k < KS; k += 128) {
            float4 va = *reinterpret_cast<const float4*>(&a[k]);
            float4 vw = *reinterpret_cast<const float4*>(&w[k]);
            p += va.x * vw.x + va.y * vw.y + va.z * vw.z + va.w * vw.w;
        }
#pragma unroll
        for (int off = 16; off > 0; off >>= 1)
            p += __shfl_xor_sync(0xffffffffu, p, off);
        ce = (m + __logf(z)) - p;
    }
    float cs = d / (fmaxf(sqrtf(ssq), 1e-12f) * fmaxf(sqrtf(tsq), 1e-12f));
    if (lane == 0) { g_row[2 * row] = ce; g_row[2 * row + 1] = cs; }
}

// ---------------------------------------------------------------------------
// K3: deterministic tree reduction to the scalar loss.
// loss = 0.5 * (ce_sum / BT) + 0.5 * (0.5 * sum(1 - cos) / BT)
// ---------------------------------------------------------------------------
__global__ void finalize_kernel(float* __restrict__ out)
{
    __shared__ float sce[256], scs[256];
    int tid = threadIdx.x;
    float ce = 0.f, cs = 0.f;
    for (int r = tid; r < BT; r += 256) {
        ce += g_row[2 * r];
        cs += 1.0f - g_row[2 * r + 1];
    }
    sce[tid] = ce; scs[tid] = cs;
    __syncthreads();
    for (int s = 128; s > 0; s >>= 1) {
        if (tid < s) { sce[tid] += sce[tid + s]; scs[tid] += scs[tid + s]; }
        __syncthreads();
    }
    if (tid == 0)
        out[0] = 0.5f * (sce[0] / (float)BT) + 0.25f * (scs[0] / (float)BT);
}

// ---------------------------------------------------------------------------
extern "C" void kernel_launch(void* const* d_in, const int* in_sizes, int n_in,
                              void* d_out, int out_size)
{
    const float* s_in = (const float*)d_in[0];
    const float* t_in = (const float*)d_in[1];
    const float* s_w  = (const float*)d_in[2];
    const float* t_w  = (const float*)d_in[3];
    const int*   tgt  = (const int*)d_in[4];
    float* out = (float*)d_out;

    int smem_bytes = (BM * (BKK + 1) + BKK * BN + BM * BN) * (int)sizeof(float);
    cudaFuncSetAttribute(fused_logits_kernel,
                         cudaFuncAttributeMaxDynamicSharedMemorySize, smem_bytes);

    dim3 grid(NTILES, BT / BM);
    fused_logits_kernel<<<grid, 256, smem_bytes>>>(s_in, t_in, s_w, t_w);
    combine_kernel<<<(BT * 32) / 256, 256>>>(tgt, s_in, s_w);
    finalize_kernel<<<1, 256>>>(out);
}

// round 3
// speedup vs baseline: 7.7897x; 7.7897x over previous
#include <cuda_runtime.h>
#include <cuda_bf16.h>
#include <math.h>
#include <float.h>
#include <stdint.h>

// ---------------- problem constants ----------------
#define BT   4096
#define KS   2048
#define KT   4096
#define VOC  32000
// ---------------- tiling ----------------
#define BM   128
#define BN   128
#define BK   64            // 128 bytes per row (bf16)
#define NT   250           // 32000/128 vocab tiles
#define NT4  1000          // NT * 4 warp_n slices
#define NPAD 1024
#define SCH  (KS/BK)       // 32 student chunks
#define NCH  (KS/BK + KT/BK)  // 96 chunks
#define NST  3
#define STAGE_B (BM*128 + BN*128)      // 32 KB
#define SMEM_BYTES (NST * STAGE_B)     // 96 KB

// ---------------- static device scratch ----------------
__device__ __nv_bfloat16 g_sin_bf[(size_t)BT * KS];
__device__ __nv_bfloat16 g_tin_bf[(size_t)BT * KT];
__device__ __nv_bfloat16 g_sw_bf [(size_t)VOC * KS];
__device__ __nv_bfloat16 g_tw_bf [(size_t)VOC * KT];

__device__ float g_m [(size_t)BT * NPAD];
__device__ float g_z [(size_t)BT * NPAD];
__device__ float g_d [(size_t)BT * NPAD];
__device__ float g_ss[(size_t)BT * NPAD];
__device__ float g_tt[(size_t)BT * NPAD];
__device__ float g_row[BT * 2];

// ---------------- PTX helpers ----------------
__device__ __forceinline__ uint32_t smem_u32(const void* p) {
    uint32_t a;
    asm("{ .reg .u64 t; cvta.to.shared.u64 t, %1; cvt.u32.u64 %0, t; }" : "=r"(a) : "l"(p));
    return a;
}
#define SWZ(o) ((o) ^ (((o) >> 3) & 0x70))

#define CP16(dst, src) \
    asm volatile("cp.async.cg.shared.global [%0], [%1], 16;" :: "r"(dst), "l"(src) : "memory")
#define CP_COMMIT() asm volatile("cp.async.commit_group;" ::: "memory")
#define CP_WAIT(n)  asm volatile("cp.async.wait_group %0;" :: "n"(n) : "memory")

#define LDSM4(r0, r1, r2, r3, a) \
    asm volatile("ldmatrix.sync.aligned.m8n8.x4.shared.b16 {%0,%1,%2,%3}, [%4];" \
        : "=r"(r0), "=r"(r1), "=r"(r2), "=r"(r3) : "r"(a))

#define MMA16816(d, a, b) \
    asm volatile("mma.sync.aligned.m16n8k16.row.col.f32.bf16.bf16.f32 " \
        "{%0,%1,%2,%3}, {%4,%5,%6,%7}, {%8,%9}, {%0,%1,%2,%3};" \
        : "+f"((d)[0]), "+f"((d)[1]), "+f"((d)[2]), "+f"((d)[3]) \
        : "r"((a)[0]), "r"((a)[1]), "r"((a)[2]), "r"((a)[3]), \
          "r"((b)[0]), "r"((b)[1]))

// ---------------- fp32 -> bf16 conversion ----------------
__global__ void cvt_kernel(const float* __restrict__ src, int which, size_t n) {
    __nv_bfloat16* dst = (which == 0) ? g_sin_bf : (which == 1) ? g_tin_bf
                       : (which == 2) ? g_sw_bf  : g_tw_bf;
    size_t i = ((size_t)blockIdx.x * blockDim.x + threadIdx.x) * 4;
    size_t stride = (size_t)gridDim.x * blockDim.x * 4;
    for (; i < n; i += stride) {
        float4 v = *reinterpret_cast<const float4*>(src + i);
        __nv_bfloat162 a = __float22bfloat162_rn(make_float2(v.x, v.y));
        __nv_bfloat162 b = __float22bfloat162_rn(make_float2(v.z, v.w));
        uint2 o;
        o.x = *reinterpret_cast<uint32_t*>(&a);
        o.y = *reinterpret_cast<uint32_t*>(&b);
        *reinterpret_cast<uint2*>(dst + i) = o;
    }
}

// ---------------- chunk loader (cp.async + SW128 swizzle) ----------------
__device__ __forceinline__ void load_chunk(int c, int st, uint32_t sb,
                                           int row0, int col0, int tid) {
    const __nv_bfloat16 *Ab, *Bb; int K, k0;
    if (c < SCH) { Ab = g_sin_bf; Bb = g_sw_bf; K = KS; k0 = c * BK; }
    else         { Ab = g_tin_bf; Bb = g_tw_bf; K = KT; k0 = (c - SCH) * BK; }
    uint32_t sA = sb + st * STAGE_B;
    uint32_t sB = sA + BM * 128;
#pragma unroll
    for (int i = 0; i < 4; i++) {              // A: 128 rows x 128B
        int ls = tid + i * 256;
        int row = ls >> 3, cb = (ls & 7) * 16;
        const char* g = (const char*)(Ab + (size_t)(row0 + row) * K + k0) + cb;
        CP16(sA + SWZ(ls * 16), g);
    }
#pragma unroll
    for (int i = 0; i < 4; i++) {              // B: 128 rows x 128B
        int ls = tid + i * 256;
        int row = ls >> 3, cb = (ls & 7) * 16;
        const char* g = (const char*)(Bb + (size_t)(col0 + row) * K + k0) + cb;
        CP16(sB + SWZ(ls * 16), g);
    }
}

// ---------------- one BK=64 chunk of MMAs ----------------
__device__ __forceinline__ void compute_chunk(float (&acc)[4][4][4],
                                              uint32_t sA, uint32_t sB,
                                              int wm, int wn, int lane) {
#pragma unroll
    for (int ks = 0; ks < 4; ks++) {
        uint32_t a[4][4];
#pragma unroll
        for (int mi = 0; mi < 4; mi++) {
            int row = wm * 64 + mi * 16 + (lane & 15);
            uint32_t off = row * 128 + ks * 32 + ((lane >> 4) << 4);
            LDSM4(a[mi][0], a[mi][1], a[mi][2], a[mi][3], sA + SWZ(off));
        }
        uint32_t b[4][2];
#pragma unroll
        for (int nj = 0; nj < 2; nj++) {
            int nrow = wn * 32 + nj * 16 + (lane & 7) + ((lane & 16) >> 1);
            uint32_t off = nrow * 128 + ks * 32 + (((lane >> 3) & 1) << 4);
            uint32_t r0, r1, r2, r3;
            LDSM4(r0, r1, r2, r3, sB + SWZ(off));
            b[2 * nj][0] = r0;     b[2 * nj][1] = r1;
            b[2 * nj + 1][0] = r2; b[2 * nj + 1][1] = r3;
        }
#pragma unroll
        for (int mi = 0; mi < 4; mi++)
#pragma unroll
            for (int ni = 0; ni < 4; ni++)
                MMA16816(acc[mi][ni], a[mi], b[ni]);
    }
}

// ---------------- main fused GEMM kernel ----------------
__global__ void __launch_bounds__(256, 1)
mma_fused_kernel() {
    extern __shared__ __align__(1024) char smem[];
    uint32_t sb = smem_u32(smem);
    const int tid = threadIdx.x, wid = tid >> 5, lane = tid & 31;
    const int wm = wid & 1, wn = wid >> 1;
    const int mt = blockIdx.x, nt = blockIdx.y;
    const int row0 = mt * BM, col0 = nt * BN;

    float accS[4][4][4], accT[4][4][4];
#pragma unroll
    for (int i = 0; i < 4; i++)
#pragma unroll
        for (int j = 0; j < 4; j++)
#pragma unroll
            for (int k = 0; k < 4; k++) { accS[i][j][k] = 0.f; accT[i][j][k] = 0.f; }

    // prologue: chunks 0,1 -> stages 0,1
    load_chunk(0, 0, sb, row0, col0, tid); CP_COMMIT();
    load_chunk(1, 1, sb, row0, col0, tid); CP_COMMIT();

    for (int c = 0; c < NCH; c++) {
        const int st = c % NST;
        if (c + 1 < NCH) CP_WAIT(1); else CP_WAIT(0);
        __syncthreads();

        const int p = c + 2;
        if (p < NCH) {                 // stage (p%NST) was freed by iter c-1
            load_chunk(p, p % NST, sb, row0, col0, tid);
            CP_COMMIT();
        }

        uint32_t sA = sb + st * STAGE_B;
        uint32_t sB = sA + BM * 128;
        if (c < SCH) compute_chunk(accS, sA, sB, wm, wn, lane);
        else         compute_chunk(accT, sA, sB, wm, wn, lane);
        __syncthreads();               // compute done before stage reuse next iters
    }

    // ---------------- epilogue: per-row partials over this warp's 32 cols ----
#pragma unroll
    for (int mi = 0; mi < 4; mi++) {
#pragma unroll
        for (int h = 0; h < 2; h++) {
            float s[8], t[8];
#pragma unroll
            for (int ni = 0; ni < 4; ni++) {
                s[2 * ni]     = accS[mi][ni][h * 2];
                s[2 * ni + 1] = accS[mi][ni][h * 2 + 1];
                t[2 * ni]     = accT[mi][ni][h * 2];
                t[2 * ni + 1] = accT[mi][ni][h * 2 + 1];
            }
            float m = s[0];
#pragma unroll
            for (int j = 1; j < 8; j++) m = fmaxf(m, s[j]);
            float z = 0.f, d = 0.f, ssq = 0.f, tsq = 0.f;
#pragma unroll
            for (int j = 0; j < 8; j++) {
                z += __expf(s[j] - m);
                d = fmaf(s[j], t[j], d);
                ssq = fmaf(s[j], s[j], ssq);
                tsq = fmaf(t[j], t[j], tsq);
            }
            // reduce across the 4 lanes sharing this row (quad)
#pragma unroll
            for (int off = 1; off < 4; off <<= 1) {
                float om = __shfl_xor_sync(0xffffffffu, m, off);
                float oz = __shfl_xor_sync(0xffffffffu, z, off);
                float od = __shfl_xor_sync(0xffffffffu, d, off);
                float os = __shfl_xor_sync(0xffffffffu, ssq, off);
                float ot = __shfl_xor_sync(0xffffffffu, tsq, off);
                float nm = fmaxf(m, om);
                z = z * __expf(m - nm) + oz * __expf(om - nm);
                m = nm;
                d += od; ssq += os; tsq += ot;
            }
            if ((lane & 3) == 0) {
                int row = row0 + wm * 64 + mi * 16 + h * 8 + (lane >> 2);
                size_t idx = (size_t)row * NPAD + nt * 4 + wn;
                g_m[idx] = m; g_z[idx] = z; g_d[idx] = d;
                g_ss[idx] = ssq; g_tt[idx] = tsq;
            }
        }
    }
}

// ---------------- K2: per-row combine + exact target logit ----------------
__global__ void combine_kernel(const int* __restrict__ tgt,
                               const float* __restrict__ s_in,
                               const float* __restrict__ s_w)
{
    int gw = (blockIdx.x * blockDim.x + threadIdx.x) >> 5;
    int lane = threadIdx.x & 31;
    if (gw >= BT) return;
    const int row = gw;

    float m = -FLT_MAX, z = 0.f, d = 0.f, ssq = 0.f, tsq = 0.f;
    for (int n = lane; n < NT4; n += 32) {
        size_t idx = (size_t)row * NPAD + n;
        float om = g_m[idx], oz = g_z[idx];
        float nm = fmaxf(m, om);
        z = z * __expf(m - nm) + oz * __expf(om - nm);
        m = nm;
        d += g_d[idx]; ssq += g_ss[idx]; tsq += g_tt[idx];
    }
#pragma unroll
    for (int off = 16; off > 0; off >>= 1) {
        float om = __shfl_xor_sync(0xffffffffu, m, off);
        float oz = __shfl_xor_sync(0xffffffffu, z, off);
        float od = __shfl_xor_sync(0xffffffffu, d, off);
        float os = __shfl_xor_sync(0xffffffffu, ssq, off);
        float ot = __shfl_xor_sync(0xffffffffu, tsq, off);
        float nm = fmaxf(m, om);
        z = z * __expf(m - nm) + oz * __expf(om - nm);
        m = nm;
        d += od; ssq += os; tsq += ot;
    }

    bool is64 = (tgt[1] == -1);            // int64 layout: high word of -100
    int t = is64 ? tgt[2 * row] : tgt[row];

    float ce = 0.f;
    if (t >= 0) {
        float p = 0.f;
        const float* a = s_in + (size_t)row * KS;
        const float* w = s_w + (size_t)t * KS;
        for (int k = lane * 4; k < KS; k += 128) {
            float4 va = *reinterpret_cast<const float4*>(&a[k]);
            float4 vw = *reinterpret_cast<const float4*>(&w[k]);
            p += va.x * vw.x + va.y * vw.y + va.z * vw.z + va.w * vw.w;
        }
#pragma unroll
        for (int off = 16; off > 0; off >>= 1)
            p += __shfl_xor_sync(0xffffffffu, p, off);
        ce = (m + __logf(z)) - p;
    }
    float cs = d / (fmaxf(sqrtf(ssq), 1e-12f) * fmaxf(sqrtf(tsq), 1e-12f));
    if (lane == 0) { g_row[2 * row] = ce; g_row[2 * row + 1] = cs; }
}

// ---------------- K3: final reduction ----------------
__global__ void finalize_kernel(float* __restrict__ out) {
    __shared__ float sce[256], scs[256];
    int tid = threadIdx.x;
    float ce = 0.f, cs = 0.f;
    for (int r = tid; r < BT; r += 256) {
        ce += g_row[2 * r];
        cs += 1.0f - g_row[2 * r + 1];
    }
    sce[tid] = ce; scs[tid] = cs;
    __syncthreads();
    for (int s = 128; s > 0; s >>= 1) {
        if (tid < s) { sce[tid] += sce[tid + s]; scs[tid] += scs[tid + s]; }
        __syncthreads();
    }
    if (tid == 0)
        out[0] = 0.5f * (sce[0] / (float)BT) + 0.25f * (scs[0] / (float)BT);
}

// ---------------- launch ----------------
extern "C" void kernel_launch(void* const* d_in, const int* in_sizes, int n_in,
                              void* d_out, int out_size)
{
    const float* s_in = (const float*)d_in[0];
    const float* t_in = (const float*)d_in[1];
    const float* s_w  = (const float*)d_in[2];
    const float* t_w  = (const float*)d_in[3];
    const int*   tgt  = (const int*)d_in[4];
    float* out = (float*)d_out;

    cudaFuncSetAttribute(mma_fused_kernel,
                         cudaFuncAttributeMaxDynamicSharedMemorySize, SMEM_BYTES);

    cvt_kernel<<<2048, 256>>>(s_in, 0, (size_t)BT * KS);
    cvt_kernel<<<2048, 256>>>(t_in, 1, (size_t)BT * KT);
    cvt_kernel<<<4096, 256>>>(s_w,  2, (size_t)VOC * KS);
    cvt_kernel<<<4096, 256>>>(t_w,  3, (size_t)VOC * KT);

    dim3 grid(BT / BM, NT);   // mtile fast -> concurrent CTAs share weight tiles in L2
    mma_fused_kernel<<<grid, 256, SMEM_BYTES>>>();

    combine_kernel<<<(BT * 32) / 256, 256>>>(tgt, s_in, s_w);
    finalize_kernel<<<1, 256>>>(out);
}